// round 6
// baseline (speedup 1.0000x reference)
#include <cuda_runtime.h>
#include <cuda_bf16.h>
#include <cstdint>

#define N_NODES 20000
#define M_PAD   20096           // 157 * 128
#define DEG     16
#define NHEAD   4
#define DH      128
#define D_ROPE  126
#define MT      157             // m tiles of 128

// ---------------- scratch (static device globals: allocation-free) ----------
__device__ __nv_bfloat16 g_xhi[M_PAD * 512];
__device__ __nv_bfloat16 g_xlo[M_PAD * 512];
__device__ float g_q[N_NODES * 512];
__device__ float g_k[N_NODES * 512];
__device__ float g_v[N_NODES * 512];
__device__ __nv_bfloat16 g_yhi[M_PAD * 512];   // pad rows stay zero (zero-init, never written)
__device__ __nv_bfloat16 g_ylo[M_PAD * 512];
__device__ __nv_bfloat16 g_whi[3 * 512 * 512]; // Wq/Wk/Wv rows permuted to head-major
__device__ __nv_bfloat16 g_wlo[3 * 512 * 512];
__device__ __nv_bfloat16 g_wohi[512 * 512];    // Wo cols permuted to head-major
__device__ __nv_bfloat16 g_wolo[512 * 512];

// ===================== PTX helpers (plain sm_103 features only) ==============
__device__ __forceinline__ uint32_t smem_to_u32(const void* p) {
    uint32_t a;
    asm("{ .reg .u64 t; cvta.to.shared.u64 t, %1; cvt.u32.u64 %0, t; }" : "=r"(a) : "l"(p));
    return a;
}
#define CP_ASYNC16(dst, src) \
    asm volatile("cp.async.cg.shared.global [%0], [%1], 16;" \
        :: "r"(dst), "l"(src) : "memory")
#define CP_COMMIT() asm volatile("cp.async.commit_group;" ::: "memory")
#define CP_WAIT(n)  asm volatile("cp.async.wait_group %0;" :: "n"(n) : "memory")

#define LDSM_X4(R, addr) \
    asm volatile("ldmatrix.sync.aligned.m8n8.x4.shared.b16 {%0,%1,%2,%3}, [%4];" \
        : "=r"((R)[0]), "=r"((R)[1]), "=r"((R)[2]), "=r"((R)[3]) : "r"(addr))

__device__ __forceinline__ void mma16816(float c[4], const uint32_t a[4],
                                         uint32_t b0, uint32_t b1) {
    asm volatile(
        "mma.sync.aligned.m16n8k16.row.col.f32.bf16.bf16.f32 "
        "{%0,%1,%2,%3}, {%4,%5,%6,%7}, {%8,%9}, {%0,%1,%2,%3};"
        : "+f"(c[0]), "+f"(c[1]), "+f"(c[2]), "+f"(c[3])
        : "r"(a[0]), "r"(a[1]), "r"(a[2]), "r"(a[3]), "r"(b0), "r"(b1));
}

// ---------------- accurate sincos for |a| <~ 200 (fast-math safe) -----------
__device__ __forceinline__ void rope_sincos(float a, float& s_out, float& c_out) {
    float j = rintf(a * 0.6366197723675814f);
    int   q = (int)j;
    float r = fmaf(j, -1.5703125f, a);
    r = fmaf(j, -4.837512969970703125e-4f, r);
    r = fmaf(j, -7.549789948768648e-8f, r);
    float r2 = r * r;
    float ss = -1.9515295891e-4f;
    ss = fmaf(ss, r2, 8.3321608736e-3f);
    ss = fmaf(ss, r2, -1.6666654611e-1f);
    ss = fmaf(ss * r2, r, r);
    float cc = 2.443315711809948e-5f;
    cc = fmaf(cc, r2, -1.388731625493765e-3f);
    cc = fmaf(cc, r2, 4.166664568298827e-2f);
    cc = fmaf(cc, r2, -0.5f);
    cc = fmaf(cc, r2, 1.0f);
    int qq = q & 3;
    float sv = (qq & 1) ? cc : ss;
    float cv = (qq & 1) ? ss : cc;
    if (qq & 2)       sv = -sv;
    if ((qq + 1) & 2) cv = -cv;
    s_out = sv; c_out = cv;
}
__device__ __forceinline__ float rope_inv_freq(int m) {
    return expf(-0.43858763676075163f * (float)m);   // exp(-m*ln(1e4)/21)
}
__device__ __forceinline__ void bf_split(float f, __nv_bfloat16& h, __nv_bfloat16& l) {
    h = __float2bfloat16(f);
    l = __float2bfloat16(f - __bfloat162float(h));
}

// ---------------- conversion kernels -----------------------------------------
__global__ void conv_x_kernel(const float* __restrict__ x) {
    int idx = blockIdx.x * 256 + threadIdx.x;   // handles 4 elems
    float4 xv = ((const float4*)x)[idx];
    __nv_bfloat16 h0, h1, h2, h3, l0, l1, l2, l3;
    bf_split(xv.x, h0, l0); bf_split(xv.y, h1, l1);
    bf_split(xv.z, h2, l2); bf_split(xv.w, h3, l3);
    ((__nv_bfloat162*)g_xhi)[2 * idx]     = __halves2bfloat162(h0, h1);
    ((__nv_bfloat162*)g_xhi)[2 * idx + 1] = __halves2bfloat162(h2, h3);
    ((__nv_bfloat162*)g_xlo)[2 * idx]     = __halves2bfloat162(l0, l1);
    ((__nv_bfloat162*)g_xlo)[2 * idx + 1] = __halves2bfloat162(l2, l3);
}

__global__ void conv_w_kernel(const float* __restrict__ Wq, const float* __restrict__ Wk,
                              const float* __restrict__ Wv, const float* __restrict__ Wo) {
    int idx = blockIdx.x * 256 + threadIdx.x;   // 0 .. 512*512-1
    int mat = blockIdx.y;
    if (mat < 3) {
        const float* W = (mat == 0) ? Wq : (mat == 1 ? Wk : Wv);
        int jg = idx >> 9, k = idx & 511;
        float f = W[(((jg & 127) << 2) + (jg >> 7)) * 512 + k];
        __nv_bfloat16 h, l; bf_split(f, h, l);
        g_whi[mat * 262144 + idx] = h;
        g_wlo[mat * 262144 + idx] = l;
    } else {
        int o = idx >> 9, j = idx & 511;
        float f = Wo[o * 512 + ((j & 127) << 2) + (j >> 7)];
        __nv_bfloat16 h, l; bf_split(f, h, l);
        g_wohi[idx] = h;
        g_wolo[idx] = l;
    }
}

// ---------------- HMMA split-bf16 mainloop ------------------------------------
// CTA tile 128(m) x 256(n), K-step 64. 8 warps, warp tile 64x64.
// smem per stage: Ahi 16K | Alo 16K | Bhi 32K | Blo 32K = 96KB, 2 stages.
#define A_TILE      16384
#define B_TILE      32768
#define STAGE_BYTES 98304
#define SMEM_BYTES  (2 * STAGE_BYTES)   // 196608

__device__ __forceinline__ void load_stage(
    uint32_t smem_u32, int b,
    const __nv_bfloat16* __restrict__ ahi, const __nv_bfloat16* __restrict__ alo,
    const __nv_bfloat16* __restrict__ bhi, const __nv_bfloat16* __restrict__ blo,
    int m0, int n0, int k0, int tid)
{
    const uint32_t buf = smem_u32 + b * STAGE_BYTES;
    // A tiles: 128 rows x 8 chunks of 16B
#pragma unroll
    for (int t = 0; t < 2; t++) {
        const __nv_bfloat16* g = t ? alo : ahi;
        const uint32_t tb = buf + t * A_TILE;
#pragma unroll
        for (int i = 0; i < 4; i++) {
            int cid = i * 256 + tid;
            int row = cid >> 3, c = cid & 7;
            uint32_t dst = tb + row * 128 + ((c ^ (row & 7)) << 4);
            CP_ASYNC16(dst, g + (size_t)(m0 + row) * 512 + k0 + c * 8);
        }
    }
    // B tiles: 256 rows x 8 chunks of 16B
#pragma unroll
    for (int t = 0; t < 2; t++) {
        const __nv_bfloat16* g = t ? blo : bhi;
        const uint32_t tb = buf + 2 * A_TILE + t * B_TILE;
#pragma unroll
        for (int i = 0; i < 8; i++) {
            int cid = i * 256 + tid;
            int row = cid >> 3, c = cid & 7;
            uint32_t dst = tb + row * 128 + ((c ^ (row & 7)) << 4);
            CP_ASYNC16(dst, g + (size_t)(n0 + row) * 512 + k0 + c * 8);
        }
    }
    CP_COMMIT();
}

// warp tile 64x64: acc[mi 0..3][nj 0..7][4]
__device__ __forceinline__ void compute_stage(
    uint32_t buf, int lane, int wm, int wn, float acc[4][8][4])
{
    const int g = lane >> 3, r = lane & 7;
    const int a_row0 = wm * 64 + ((g & 1) << 3) + r;
    const int a_ch0  = g >> 1;
    const int b_row0 = wn * 64 + ((g >> 1) << 3) + r;
    const int b_ch0  = g & 1;

#pragma unroll
    for (int kb = 0; kb < 4; kb++) {
        uint32_t ah[4][4], al[4][4];
#pragma unroll
        for (int mi = 0; mi < 4; mi++) {
            int row = a_row0 + mi * 16;
            int ch  = 2 * kb + a_ch0;
            uint32_t off = row * 128 + ((ch ^ (row & 7)) << 4);
            LDSM_X4(ah[mi], buf + off);
            LDSM_X4(al[mi], buf + A_TILE + off);
        }
        uint32_t bh[4][4], bl[4][4];  // [nb]: regs {0,1}=n8 frag 2nb, {2,3}=frag 2nb+1
#pragma unroll
        for (int nb = 0; nb < 4; nb++) {
            int row = b_row0 + nb * 16;
            int ch  = 2 * kb + b_ch0;
            uint32_t off = row * 128 + ((ch ^ (row & 7)) << 4);
            LDSM_X4(bh[nb], buf + 2 * A_TILE + off);
            LDSM_X4(bl[nb], buf + 2 * A_TILE + B_TILE + off);
        }
#pragma unroll
        for (int mi = 0; mi < 4; mi++) {
#pragma unroll
            for (int nj = 0; nj < 8; nj++) {
                uint32_t b0h = bh[nj >> 1][(nj & 1) * 2], b1h = bh[nj >> 1][(nj & 1) * 2 + 1];
                uint32_t b0l = bl[nj >> 1][(nj & 1) * 2], b1l = bl[nj >> 1][(nj & 1) * 2 + 1];
                mma16816(acc[mi][nj], ah[mi], b0h, b1h);   // hi*hi
                mma16816(acc[mi][nj], ah[mi], b0l, b1l);   // hi*lo
                mma16816(acc[mi][nj], al[mi], b0h, b1h);   // lo*hi
            }
        }
    }
}

__device__ __forceinline__ void gemm_mainloop(
    const __nv_bfloat16* __restrict__ ahi, const __nv_bfloat16* __restrict__ alo,
    const __nv_bfloat16* __restrict__ bhi, const __nv_bfloat16* __restrict__ blo,
    int m0, int n0, uint32_t smem_u32, int tid, int lane, int wm, int wn,
    float acc[4][8][4])
{
#pragma unroll
    for (int mi = 0; mi < 4; mi++)
#pragma unroll
        for (int nj = 0; nj < 8; nj++)
#pragma unroll
            for (int q = 0; q < 4; q++) acc[mi][nj][q] = 0.f;

    load_stage(smem_u32, 0, ahi, alo, bhi, blo, m0, n0, 0, tid);
#pragma unroll 1
    for (int s = 0; s < 8; s++) {
        if (s < 7) {
            load_stage(smem_u32, (s + 1) & 1, ahi, alo, bhi, blo, m0, n0, (s + 1) * 64, tid);
            CP_WAIT(1);
        } else {
            CP_WAIT(0);
        }
        __syncthreads();
        compute_stage(smem_u32 + (s & 1) * STAGE_BYTES, lane, wm, wn, acc);
        __syncthreads();
    }
}

// ---------------- QKV GEMM (+bias, +q-scale, +RoPE) ---------------------------
__global__ __launch_bounds__(256, 1)
void qkv_tc_kernel(const float* __restrict__ pos,
                   const float* __restrict__ bq, const float* __restrict__ bk,
                   const float* __restrict__ bv)
{
    extern __shared__ __align__(1024) char smem[];
    const uint32_t smem_u32 = smem_to_u32(smem);
    const int tid  = threadIdx.x;
    const int lane = tid & 31;
    const int w    = tid >> 5;
    const int wm   = w & 1, wn = w >> 1;   // wm 0..1, wn 0..3
    const int m0   = blockIdx.x * 128;
    const int n0   = blockIdx.y * 256;     // spans 2 heads
    const int mode = blockIdx.z;           // 0=q, 1=k, 2=v

    const __nv_bfloat16* bh = g_whi + (size_t)mode * 262144;
    const __nv_bfloat16* bl = g_wlo + (size_t)mode * 262144;

    float acc[4][8][4];
    gemm_mainloop(g_xhi, g_xlo, bh, bl, m0, n0, smem_u32, tid, lane, wm, wn, acc);

    // ---- epilogue ----
    const float* bias = (mode == 0) ? bq : (mode == 1 ? bk : bv);
    const float rs = (mode == 0) ? 0.08838834764831845f : 1.0f;   // 1/sqrt(128)
    float* outp = (mode == 0) ? g_q : (mode == 1 ? g_k : g_v);
    const int tg = lane >> 2, tq = lane & 3;

#pragma unroll
    for (int mi = 0; mi < 4; mi++) {
#pragma unroll
        for (int half = 0; half < 2; half++) {
            int row = m0 + wm * 64 + mi * 16 + half * 8 + tg;
            if (row >= N_NODES) continue;
            float p0 = 0.f, p1 = 0.f, p2 = 0.f;
            if (mode != 2) {
                p0 = pos[row * 3 + 0]; p1 = pos[row * 3 + 1]; p2 = pos[row * 3 + 2];
            }
#pragma unroll
            for (int nj = 0; nj < 8; nj++) {
                int col  = n0 + wn * 64 + nj * 8 + tq * 2;
                int head = col >> 7;
                int d    = col & 127;
                float v0 = (acc[mi][nj][half * 2 + 0] + __ldg(&bias[d * 4 + head])) * rs;
                float v1 = (acc[mi][nj][half * 2 + 1] + __ldg(&bias[(d + 1) * 4 + head])) * rs;
                if (mode != 2 && d < D_ROPE) {
                    int pp = (d >= 84) ? 2 : ((d >= 42) ? 1 : 0);
                    int mf = (d - pp * 42) >> 1;
                    float ps = (pp == 0) ? p0 : (pp == 1 ? p1 : p2);
                    float ang = ps * rope_inv_freq(mf);
                    float sn, cs;
                    rope_sincos(ang, sn, cs);
                    float ev = v0, od = v1;
                    v0 = ev * cs - od * sn;
                    v1 = ev * sn + od * cs;
                }
                *(float2*)(outp + (size_t)row * 512 + col) = make_float2(v0, v1);
            }
        }
    }
}

// ---------------- output projection GEMM --------------------------------------
__global__ __launch_bounds__(256, 1)
void out_tc_kernel(const float* __restrict__ bo, float* __restrict__ out)
{
    extern __shared__ __align__(1024) char smem[];
    const uint32_t smem_u32 = smem_to_u32(smem);
    const int tid  = threadIdx.x;
    const int lane = tid & 31;
    const int w    = tid >> 5;
    const int wm   = w & 1, wn = w >> 1;
    const int m0   = blockIdx.x * 128;
    const int n0   = blockIdx.y * 256;

    float acc[4][8][4];
    gemm_mainloop(g_yhi, g_ylo, g_wohi, g_wolo, m0, n0, smem_u32, tid, lane, wm, wn, acc);

    const int tg = lane >> 2, tq = lane & 3;
#pragma unroll
    for (int mi = 0; mi < 4; mi++) {
#pragma unroll
        for (int half = 0; half < 2; half++) {
            int row = m0 + wm * 64 + mi * 16 + half * 8 + tg;
            if (row >= N_NODES) continue;
#pragma unroll
            for (int nj = 0; nj < 8; nj++) {
                int col = n0 + wn * 64 + nj * 8 + tq * 2;
                float v0 = acc[mi][nj][half * 2 + 0] + __ldg(&bo[col]);
                float v1 = acc[mi][nj][half * 2 + 1] + __ldg(&bo[col + 1]);
                *(float2*)(out + (size_t)row * 512 + col) = make_float2(v0, v1);
            }
        }
    }
}

// ---------------- per-node 16-edge softmax attention --------------------------
// 2 nodes per block (256 threads); warp = (node_sub, head); lane = 4 d's.
__global__ __launch_bounds__(256)
void attn_kernel(const int* __restrict__ cols) {
    const int nsub = threadIdx.x >> 7;            // 0..1
    const int i    = blockIdx.x * 2 + nsub;
    const int hh   = (threadIdx.x >> 5) & 3;
    const int lane = threadIdx.x & 31;

    __shared__ int scol[2][DEG];
    if (threadIdx.x < 32) scol[threadIdx.x >> 4][threadIdx.x & 15] =
        cols[blockIdx.x * 32 + threadIdx.x];
    __syncthreads();

    const int off = i * 512 + hh * DH + lane * 4;
    const float4 q4 = *(const float4*)(g_q + off);

    // per-lane partial dot products for all 16 edges (batched loads -> MLP)
    float part[DEG];
#pragma unroll
    for (int e = 0; e < DEG; e++) {
        int c = scol[nsub][e];
        float4 k4 = *(const float4*)(g_k + c * 512 + hh * DH + lane * 4);
        float s = q4.x * k4.x;
        s = fmaf(q4.y, k4.y, s);
        s = fmaf(q4.z, k4.z, s);
        s = fmaf(q4.w, k4.w, s);
        part[e] = s;
    }

    // multi-value butterfly: lane L ends with total for edge e = L & 15
#pragma unroll
    for (int j = 0; j < 16; j++)
        part[j] += __shfl_xor_sync(0xffffffffu, part[j], 16);
    float r8[8];
#pragma unroll
    for (int j = 0; j < 8; j++) {
        float keep = (lane & 8) ? part[j + 8] : part[j];
        float send = (lane & 8) ? part[j]     : part[j + 8];
        r8[j] = keep + __shfl_xor_sync(0xffffffffu, send, 8);
    }
    float r4[4];
#pragma unroll
    for (int j = 0; j < 4; j++) {
        float keep = (lane & 4) ? r8[j + 4] : r8[j];
        float send = (lane & 4) ? r8[j]     : r8[j + 4];
        r4[j] = keep + __shfl_xor_sync(0xffffffffu, send, 4);
    }
    float r2[2];
#pragma unroll
    for (int j = 0; j < 2; j++) {
        float keep = (lane & 2) ? r4[j + 2] : r4[j];
        float send = (lane & 2) ? r4[j]     : r4[j + 2];
        r2[j] = keep + __shfl_xor_sync(0xffffffffu, send, 2);
    }
    float keep1 = (lane & 1) ? r2[1] : r2[0];
    float send1 = (lane & 1) ? r2[0] : r2[1];
    float sc = keep1 + __shfl_xor_sync(0xffffffffu, send1, 1);
    // sc at lane L = score of edge (L & 15)

    float mx = sc;
    mx = fmaxf(mx, __shfl_xor_sync(0xffffffffu, mx, 8));
    mx = fmaxf(mx, __shfl_xor_sync(0xffffffffu, mx, 4));
    mx = fmaxf(mx, __shfl_xor_sync(0xffffffffu, mx, 2));
    mx = fmaxf(mx, __shfl_xor_sync(0xffffffffu, mx, 1));

    float p = expf(sc - mx);
    float denom = p;
    denom += __shfl_xor_sync(0xffffffffu, denom, 8);
    denom += __shfl_xor_sync(0xffffffffu, denom, 4);
    denom += __shfl_xor_sync(0xffffffffu, denom, 2);
    denom += __shfl_xor_sync(0xffffffffu, denom, 1);
    float attn = p / denom;

    float4 acc = make_float4(0.f, 0.f, 0.f, 0.f);
#pragma unroll
    for (int e = 0; e < DEG; e++) {
        int c = scol[nsub][e];
        float pe = __shfl_sync(0xffffffffu, attn, e);
        float4 v4 = *(const float4*)(g_v + c * 512 + hh * DH + lane * 4);
        acc.x = fmaf(pe, v4.x, acc.x);
        acc.y = fmaf(pe, v4.y, acc.y);
        acc.z = fmaf(pe, v4.z, acc.z);
        acc.w = fmaf(pe, v4.w, acc.w);
    }

    // split-bf16 store of y for the output projection
    __nv_bfloat16 h0, h1, h2, h3, l0, l1, l2, l3;
    bf_split(acc.x, h0, l0); bf_split(acc.y, h1, l1);
    bf_split(acc.z, h2, l2); bf_split(acc.w, h3, l3);
    __nv_bfloat162* yh = (__nv_bfloat162*)(g_yhi + off);
    __nv_bfloat162* yl = (__nv_bfloat162*)(g_ylo + off);
    yh[0] = __halves2bfloat162(h0, h1);
    yh[1] = __halves2bfloat162(h2, h3);
    yl[0] = __halves2bfloat162(l0, l1);
    yl[1] = __halves2bfloat162(l2, l3);
}

// -----------------------------------------------------------------------------
extern "C" void kernel_launch(void* const* d_in, const int* in_sizes, int n_in,
                              void* d_out, int out_size) {
    const float* x   = (const float*)d_in[0];
    const float* pos = (const float*)d_in[1];
    // d_in[2] = rows (implicit: node i owns edges [16i, 16i+16))
    const int*   cols = (const int*)d_in[3];
    const float* Wq = (const float*)d_in[4];
    const float* bq = (const float*)d_in[5];
    const float* Wk = (const float*)d_in[6];
    const float* bk = (const float*)d_in[7];
    const float* Wv = (const float*)d_in[8];
    const float* bv = (const float*)d_in[9];
    const float* Wo = (const float*)d_in[10];
    const float* bo = (const float*)d_in[11];
    float* out = (float*)d_out;

    static bool attr_set = false;
    if (!attr_set) {
        cudaFuncSetAttribute(qkv_tc_kernel, cudaFuncAttributeMaxDynamicSharedMemorySize, SMEM_BYTES);
        cudaFuncSetAttribute(out_tc_kernel, cudaFuncAttributeMaxDynamicSharedMemorySize, SMEM_BYTES);
        attr_set = true;
    }

    conv_x_kernel<<<(N_NODES * 512 / 4) / 256, 256>>>(x);
    conv_w_kernel<<<dim3(512 * 512 / 256, 4), 256>>>(Wq, Wk, Wv, Wo);

    qkv_tc_kernel<<<dim3(MT, 2, 3), 256, SMEM_BYTES>>>(pos, bq, bk, bv);

    attn_kernel<<<N_NODES / 2, 256>>>(cols);

    out_tc_kernel<<<dim3(MT, 2), 256, SMEM_BYTES>>>(bo, out);
}

// round 9
// speedup vs baseline: 1.4963x; 1.4963x over previous
#include <cuda_runtime.h>
#include <cuda_fp16.h>
#include <cstdint>

#define N_NODES 20000
#define M_PAD   20096           // 157 * 128
#define DEG     16
#define NHEAD   4
#define DH      128
#define D_ROPE  126
#define MT      157             // m tiles of 128

// ---------------- scratch (static device globals: allocation-free) ----------
__device__ __half g_xhi[M_PAD * 512];
__device__ __half g_xlo[M_PAD * 512];
__device__ float g_q[N_NODES * 512];
__device__ float g_k[N_NODES * 512];
__device__ float g_v[N_NODES * 512];
__device__ __half g_yhi[M_PAD * 512];   // pad rows stay zero (zero-init, never written)
__device__ __half g_ylo[M_PAD * 512];
__device__ __half g_whi[3 * 512 * 512]; // Wq/Wk/Wv rows permuted to head-major (fp16 hi only)
__device__ __half g_wohi[512 * 512];    // Wo cols permuted to head-major

// ===================== PTX helpers (plain sm_103 features only) ==============
__device__ __forceinline__ uint32_t smem_to_u32(const void* p) {
    uint32_t a;
    asm("{ .reg .u64 t; cvta.to.shared.u64 t, %1; cvt.u32.u64 %0, t; }" : "=r"(a) : "l"(p));
    return a;
}
#define CP_ASYNC16(dst, src) \
    asm volatile("cp.async.cg.shared.global [%0], [%1], 16;" \
        :: "r"(dst), "l"(src) : "memory")
#define CP_COMMIT() asm volatile("cp.async.commit_group;" ::: "memory")
#define CP_WAIT(n)  asm volatile("cp.async.wait_group %0;" :: "n"(n) : "memory")

#define LDSM_X4(R, addr) \
    asm volatile("ldmatrix.sync.aligned.m8n8.x4.shared.b16 {%0,%1,%2,%3}, [%4];" \
        : "=r"((R)[0]), "=r"((R)[1]), "=r"((R)[2]), "=r"((R)[3]) : "r"(addr))

__device__ __forceinline__ void mma16816(float c[4], const uint32_t a[4],
                                         uint32_t b0, uint32_t b1) {
    asm volatile(
        "mma.sync.aligned.m16n8k16.row.col.f32.f16.f16.f32 "
        "{%0,%1,%2,%3}, {%4,%5,%6,%7}, {%8,%9}, {%0,%1,%2,%3};"
        : "+f"(c[0]), "+f"(c[1]), "+f"(c[2]), "+f"(c[3])
        : "r"(a[0]), "r"(a[1]), "r"(a[2]), "r"(a[3]), "r"(b0), "r"(b1));
}

// ---------------- accurate sincos for |a| <~ 200 (fast-math safe) -----------
__device__ __forceinline__ void rope_sincos(float a, float& s_out, float& c_out) {
    float j = rintf(a * 0.6366197723675814f);
    int   q = (int)j;
    float r = fmaf(j, -1.5703125f, a);
    r = fmaf(j, -4.837512969970703125e-4f, r);
    r = fmaf(j, -7.549789948768648e-8f, r);
    float r2 = r * r;
    float ss = -1.9515295891e-4f;
    ss = fmaf(ss, r2, 8.3321608736e-3f);
    ss = fmaf(ss, r2, -1.6666654611e-1f);
    ss = fmaf(ss * r2, r, r);
    float cc = 2.443315711809948e-5f;
    cc = fmaf(cc, r2, -1.388731625493765e-3f);
    cc = fmaf(cc, r2, 4.166664568298827e-2f);
    cc = fmaf(cc, r2, -0.5f);
    cc = fmaf(cc, r2, 1.0f);
    int qq = q & 3;
    float sv = (qq & 1) ? cc : ss;
    float cv = (qq & 1) ? ss : cc;
    if (qq & 2)       sv = -sv;
    if ((qq + 1) & 2) cv = -cv;
    s_out = sv; c_out = cv;
}
__device__ __forceinline__ float rope_inv_freq(int m) {
    return expf(-0.43858763676075163f * (float)m);   // exp(-m*ln(1e4)/21)
}
__device__ __forceinline__ void hf_split(float f, __half& h, __half& l) {
    h = __float2half_rn(f);
    l = __float2half_rn(f - __half2float(h));
}

// ---------------- conversion kernels -----------------------------------------
__global__ void conv_x_kernel(const float* __restrict__ x) {
    int idx = blockIdx.x * 256 + threadIdx.x;   // handles 4 elems
    float4 xv = ((const float4*)x)[idx];
    __half h0, h1, h2, h3, l0, l1, l2, l3;
    hf_split(xv.x, h0, l0); hf_split(xv.y, h1, l1);
    hf_split(xv.z, h2, l2); hf_split(xv.w, h3, l3);
    ((__half2*)g_xhi)[2 * idx]     = __halves2half2(h0, h1);
    ((__half2*)g_xhi)[2 * idx + 1] = __halves2half2(h2, h3);
    ((__half2*)g_xlo)[2 * idx]     = __halves2half2(l0, l1);
    ((__half2*)g_xlo)[2 * idx + 1] = __halves2half2(l2, l3);
}

__global__ void conv_w_kernel(const float* __restrict__ Wq, const float* __restrict__ Wk,
                              const float* __restrict__ Wv, const float* __restrict__ Wo) {
    int idx = blockIdx.x * 256 + threadIdx.x;   // 0 .. 512*512-1
    int mat = blockIdx.y;
    if (mat < 3) {
        const float* W = (mat == 0) ? Wq : (mat == 1 ? Wk : Wv);
        int jg = idx >> 9, k = idx & 511;
        g_whi[mat * 262144 + idx] =
            __float2half_rn(W[(((jg & 127) << 2) + (jg >> 7)) * 512 + k]);
    } else {
        int o = idx >> 9, j = idx & 511;
        g_wohi[idx] = __float2half_rn(Wo[o * 512 + ((j & 127) << 2) + (j >> 7)]);
    }
}

// ---------------- HMMA fp16 2-pass mainloop -----------------------------------
// CTA tile 128x128, K-step 64. smem per stage: Ahi 16K | Alo 16K | Bhi 16K.
#define TILE_BYTES  16384
#define STAGE_BYTES (3 * TILE_BYTES)
#define SMEM_BYTES  (2 * STAGE_BYTES)   // 98304 -> 2 CTAs/SM possible

__device__ __forceinline__ void load_stage(
    uint32_t smem_u32, int b,
    const __half* __restrict__ ahi, const __half* __restrict__ alo,
    const __half* __restrict__ bhi,
    int m0, int n0, int k0, int tid)
{
    const __half* src[3] = { ahi, alo, bhi };
    const uint32_t buf = smem_u32 + b * STAGE_BYTES;
#pragma unroll
    for (int t = 0; t < 3; t++) {
        const __half* g = src[t];
        const int r0 = (t < 2) ? m0 : n0;
        const uint32_t tb = buf + t * TILE_BYTES;
#pragma unroll
        for (int i = 0; i < 4; i++) {
            int cid = i * 256 + tid;          // 0..1023
            int row = cid >> 3, c = cid & 7;  // 128 rows x 8 chunks of 16B
            uint32_t dst = tb + row * 128 + ((c ^ (row & 7)) << 4);
            CP_ASYNC16(dst, g + (size_t)(r0 + row) * 512 + k0 + c * 8);
        }
    }
    CP_COMMIT();
}

// warp tile 64(m) x 32(n): acc[mi 0..3][ni 0..3][4]
__device__ __forceinline__ void compute_stage(
    uint32_t buf, int lane, int wm, int wn, float acc[4][4][4])
{
    const int g = lane >> 3, r = lane & 7;
    const int a_row0 = wm * 64 + ((g & 1) << 3) + r;
    const int a_ch0  = g >> 1;
    const int b_row0 = wn * 32 + ((g >> 1) << 3) + r;
    const int b_ch0  = g & 1;

#pragma unroll
    for (int kb = 0; kb < 4; kb++) {
        uint32_t ah[4][4], al[4][4];
#pragma unroll
        for (int mi = 0; mi < 4; mi++) {
            int row = a_row0 + mi * 16;
            int ch  = 2 * kb + a_ch0;
            uint32_t off = row * 128 + ((ch ^ (row & 7)) << 4);
            LDSM_X4(ah[mi], buf + off);
            LDSM_X4(al[mi], buf + TILE_BYTES + off);
        }
        uint32_t bh[2][4];   // [nb]: regs {0,1}=n8 frag 2nb, {2,3}=frag 2nb+1
#pragma unroll
        for (int nb = 0; nb < 2; nb++) {
            int row = b_row0 + nb * 16;
            int ch  = 2 * kb + b_ch0;
            uint32_t off = row * 128 + ((ch ^ (row & 7)) << 4);
            LDSM_X4(bh[nb], buf + 2 * TILE_BYTES + off);
        }
#pragma unroll
        for (int mi = 0; mi < 4; mi++) {
#pragma unroll
            for (int ni = 0; ni < 4; ni++) {
                uint32_t b0 = bh[ni >> 1][(ni & 1) * 2], b1 = bh[ni >> 1][(ni & 1) * 2 + 1];
                mma16816(acc[mi][ni], ah[mi], b0, b1);   // xh * wh
                mma16816(acc[mi][ni], al[mi], b0, b1);   // xl * wh
            }
        }
    }
}

__device__ __forceinline__ void gemm_mainloop(
    const __half* __restrict__ ahi, const __half* __restrict__ alo,
    const __half* __restrict__ bhi,
    int m0, int n0, uint32_t smem_u32, int tid, int lane, int wm, int wn,
    float acc[4][4][4])
{
#pragma unroll
    for (int mi = 0; mi < 4; mi++)
#pragma unroll
        for (int ni = 0; ni < 4; ni++)
#pragma unroll
            for (int q = 0; q < 4; q++) acc[mi][ni][q] = 0.f;

    load_stage(smem_u32, 0, ahi, alo, bhi, m0, n0, 0, tid);
#pragma unroll 1
    for (int s = 0; s < 8; s++) {
        if (s < 7) {
            load_stage(smem_u32, (s + 1) & 1, ahi, alo, bhi, m0, n0, (s + 1) * 64, tid);
            CP_WAIT(1);
        } else {
            CP_WAIT(0);
        }
        __syncthreads();
        compute_stage(smem_u32 + (s & 1) * STAGE_BYTES, lane, wm, wn, acc);
        __syncthreads();
    }
}

// ---------------- QKV GEMM (+bias, +q-scale, +RoPE) ---------------------------
__global__ __launch_bounds__(256, 2)
void qkv_tc_kernel(const float* __restrict__ pos,
                   const float* __restrict__ bq, const float* __restrict__ bk,
                   const float* __restrict__ bv)
{
    extern __shared__ __align__(1024) char smem[];
    const uint32_t smem_u32 = smem_to_u32(smem);
    const int tid  = threadIdx.x;
    const int lane = tid & 31;
    const int w    = tid >> 5;
    const int wm   = w & 1, wn = w >> 1;   // wm 0..1, wn 0..3
    const int m0   = blockIdx.x * 128;
    const int head = blockIdx.y;
    const int mode = blockIdx.z;           // 0=q, 1=k, 2=v
    const int n0   = head * 128;

    const __half* bh = g_whi + (size_t)mode * 262144;

    float acc[4][4][4];
    gemm_mainloop(g_xhi, g_xlo, bh, m0, n0, smem_u32, tid, lane, wm, wn, acc);

    // ---- epilogue ----
    const float* bias = (mode == 0) ? bq : (mode == 1 ? bk : bv);
    const float rs = (mode == 0) ? 0.08838834764831845f : 1.0f;   // 1/sqrt(128)
    float* outp = (mode == 0) ? g_q : (mode == 1 ? g_k : g_v);
    const int tg = lane >> 2, tq = lane & 3;

#pragma unroll
    for (int mi = 0; mi < 4; mi++) {
#pragma unroll
        for (int half = 0; half < 2; half++) {
            int row = m0 + wm * 64 + mi * 16 + half * 8 + tg;
            if (row >= N_NODES) continue;
            float p0 = 0.f, p1 = 0.f, p2 = 0.f;
            if (mode != 2) {
                p0 = pos[row * 3 + 0]; p1 = pos[row * 3 + 1]; p2 = pos[row * 3 + 2];
            }
#pragma unroll
            for (int ni = 0; ni < 4; ni++) {
                int d = wn * 32 + ni * 8 + tq * 2;
                float v0 = (acc[mi][ni][half * 2 + 0] + __ldg(&bias[d * 4 + head])) * rs;
                float v1 = (acc[mi][ni][half * 2 + 1] + __ldg(&bias[(d + 1) * 4 + head])) * rs;
                if (mode != 2 && d < D_ROPE) {
                    int pp = (d >= 84) ? 2 : ((d >= 42) ? 1 : 0);
                    int mf = (d - pp * 42) >> 1;
                    float ps = (pp == 0) ? p0 : (pp == 1 ? p1 : p2);
                    float ang = ps * rope_inv_freq(mf);
                    float sn, cs;
                    rope_sincos(ang, sn, cs);
                    float ev = v0, od = v1;
                    v0 = ev * cs - od * sn;
                    v1 = ev * sn + od * cs;
                }
                *(float2*)(outp + (size_t)row * 512 + head * DH + d) = make_float2(v0, v1);
            }
        }
    }
}

// ---------------- output projection GEMM --------------------------------------
__global__ __launch_bounds__(256, 2)
void out_tc_kernel(const float* __restrict__ bo, float* __restrict__ out)
{
    extern __shared__ __align__(1024) char smem[];
    const uint32_t smem_u32 = smem_to_u32(smem);
    const int tid  = threadIdx.x;
    const int lane = tid & 31;
    const int w    = tid >> 5;
    const int wm   = w & 1, wn = w >> 1;
    const int m0   = blockIdx.x * 128;
    const int n0   = blockIdx.y * 128;

    const __half* bh = g_wohi + (size_t)n0 * 512;

    float acc[4][4][4];
    gemm_mainloop(g_yhi, g_ylo, bh, m0, 0, smem_u32, tid, lane, wm, wn, acc);

    const int tg = lane >> 2, tq = lane & 3;
#pragma unroll
    for (int mi = 0; mi < 4; mi++) {
#pragma unroll
        for (int half = 0; half < 2; half++) {
            int row = m0 + wm * 64 + mi * 16 + half * 8 + tg;
            if (row >= N_NODES) continue;
#pragma unroll
            for (int ni = 0; ni < 4; ni++) {
                int d = wn * 32 + ni * 8 + tq * 2;
                float v0 = acc[mi][ni][half * 2 + 0] + __ldg(&bo[n0 + d]);
                float v1 = acc[mi][ni][half * 2 + 1] + __ldg(&bo[n0 + d + 1]);
                *(float2*)(out + (size_t)row * 512 + n0 + d) = make_float2(v0, v1);
            }
        }
    }
}

// ---------------- per-node 16-edge softmax attention --------------------------
// block = node, warp = head, lane = 4 consecutive d's (float4). (R5 version)
__global__ __launch_bounds__(128)
void attn_kernel(const int* __restrict__ cols) {
    const int i    = blockIdx.x;
    const int hh   = threadIdx.x >> 5;
    const int lane = threadIdx.x & 31;

    __shared__ int scol[DEG];
    if (threadIdx.x < DEG) scol[threadIdx.x] = cols[i * DEG + threadIdx.x];
    __syncthreads();

    const int off = i * 512 + hh * DH + lane * 4;
    const float4 q4 = *(const float4*)(g_q + off);

    float sc = -1e30f;
#pragma unroll
    for (int e = 0; e < DEG; e++) {
        int c = scol[e];
        float4 k4 = *(const float4*)(g_k + c * 512 + hh * DH + lane * 4);
        float s = q4.x * k4.x;
        s = fmaf(q4.y, k4.y, s);
        s = fmaf(q4.z, k4.z, s);
        s = fmaf(q4.w, k4.w, s);
        s += __shfl_xor_sync(0xffffffffu, s, 16);
        s += __shfl_xor_sync(0xffffffffu, s, 8);
        s += __shfl_xor_sync(0xffffffffu, s, 4);
        s += __shfl_xor_sync(0xffffffffu, s, 2);
        s += __shfl_xor_sync(0xffffffffu, s, 1);
        if (lane == e) sc = s;
    }

    float mx = sc;
    mx = fmaxf(mx, __shfl_xor_sync(0xffffffffu, mx, 8));
    mx = fmaxf(mx, __shfl_xor_sync(0xffffffffu, mx, 4));
    mx = fmaxf(mx, __shfl_xor_sync(0xffffffffu, mx, 2));
    mx = fmaxf(mx, __shfl_xor_sync(0xffffffffu, mx, 1));

    float p = expf(sc - mx);
    float denom = p;
    denom += __shfl_xor_sync(0xffffffffu, denom, 8);
    denom += __shfl_xor_sync(0xffffffffu, denom, 4);
    denom += __shfl_xor_sync(0xffffffffu, denom, 2);
    denom += __shfl_xor_sync(0xffffffffu, denom, 1);
    float attn = p / denom;

    float4 acc = make_float4(0.f, 0.f, 0.f, 0.f);
#pragma unroll
    for (int e = 0; e < DEG; e++) {
        int c = scol[e];
        float pe = __shfl_sync(0xffffffffu, attn, e);
        float4 v4 = *(const float4*)(g_v + c * 512 + hh * DH + lane * 4);
        acc.x = fmaf(pe, v4.x, acc.x);
        acc.y = fmaf(pe, v4.y, acc.y);
        acc.z = fmaf(pe, v4.z, acc.z);
        acc.w = fmaf(pe, v4.w, acc.w);
    }

    // split-fp16 store of y for the output projection
    __half h0, h1, h2, h3, l0, l1, l2, l3;
    hf_split(acc.x, h0, l0); hf_split(acc.y, h1, l1);
    hf_split(acc.z, h2, l2); hf_split(acc.w, h3, l3);
    __half2* yh = (__half2*)(g_yhi + off);
    __half2* yl = (__half2*)(g_ylo + off);
    yh[0] = __halves2half2(h0, h1);
    yh[1] = __halves2half2(h2, h3);
    yl[0] = __halves2half2(l0, l1);
    yl[1] = __halves2half2(l2, l3);
}

// -----------------------------------------------------------------------------
extern "C" void kernel_launch(void* const* d_in, const int* in_sizes, int n_in,
                              void* d_out, int out_size) {
    const float* x   = (const float*)d_in[0];
    const float* pos = (const float*)d_in[1];
    // d_in[2] = rows (implicit: node i owns edges [16i, 16i+16))
    const int*   cols = (const int*)d_in[3];
    const float* Wq = (const float*)d_in[4];
    const float* bq = (const float*)d_in[5];
    const float* Wk = (const float*)d_in[6];
    const float* bk = (const float*)d_in[7];
    const float* Wv = (const float*)d_in[8];
    const float* bv = (const float*)d_in[9];
    const float* Wo = (const float*)d_in[10];
    const float* bo = (const float*)d_in[11];
    float* out = (float*)d_out;

    static bool attr_set = false;
    if (!attr_set) {
        cudaFuncSetAttribute(qkv_tc_kernel, cudaFuncAttributeMaxDynamicSharedMemorySize, SMEM_BYTES);
        cudaFuncSetAttribute(out_tc_kernel, cudaFuncAttributeMaxDynamicSharedMemorySize, SMEM_BYTES);
        attr_set = true;
    }

    conv_x_kernel<<<(N_NODES * 512 / 4) / 256, 256>>>(x);
    conv_w_kernel<<<dim3(512 * 512 / 256, 4), 256>>>(Wq, Wk, Wv, Wo);

    qkv_tc_kernel<<<dim3(MT, NHEAD, 3), 256, SMEM_BYTES>>>(pos, bq, bk, bv);

    attn_kernel<<<N_NODES, 128>>>(cols);

    out_tc_kernel<<<dim3(MT, NHEAD), 256, SMEM_BYTES>>>(bo, out);
}

// round 10
// speedup vs baseline: 1.5925x; 1.0642x over previous
#include <cuda_runtime.h>
#include <cuda_fp16.h>
#include <cstdint>

#define N_NODES 20000
#define M_PAD   20096           // 157 * 128
#define DEG     16
#define NHEAD   4
#define DH      128
#define D_ROPE  126
#define MT      157             // m tiles of 128

// ---------------- scratch (static device globals: allocation-free) ----------
__device__ __half g_xhi[M_PAD * 512];
__device__ __half g_xlo[M_PAD * 512];
__device__ float  g_q[N_NODES * 512];
__device__ __half g_kh[N_NODES * 512];  // fp16 k (post-RoPE)
__device__ __half g_vh[N_NODES * 512];  // fp16 v
__device__ __half g_yhi[M_PAD * 512];   // pad rows stay zero (zero-init, never written)
__device__ __half g_ylo[M_PAD * 512];
__device__ __half g_whi[3 * 512 * 512]; // Wq/Wk/Wv rows permuted to head-major (fp16 hi)
__device__ __half g_wohi[512 * 512];    // Wo cols permuted to head-major

// ===================== PTX helpers (plain sm_103 features only) ==============
__device__ __forceinline__ uint32_t smem_to_u32(const void* p) {
    uint32_t a;
    asm("{ .reg .u64 t; cvta.to.shared.u64 t, %1; cvt.u32.u64 %0, t; }" : "=r"(a) : "l"(p));
    return a;
}
#define CP_ASYNC16(dst, src) \
    asm volatile("cp.async.cg.shared.global [%0], [%1], 16;" \
        :: "r"(dst), "l"(src) : "memory")
#define CP_COMMIT() asm volatile("cp.async.commit_group;" ::: "memory")
#define CP_WAIT(n)  asm volatile("cp.async.wait_group %0;" :: "n"(n) : "memory")

#define LDSM_X4(R, addr) \
    asm volatile("ldmatrix.sync.aligned.m8n8.x4.shared.b16 {%0,%1,%2,%3}, [%4];" \
        : "=r"((R)[0]), "=r"((R)[1]), "=r"((R)[2]), "=r"((R)[3]) : "r"(addr))

__device__ __forceinline__ void mma16816(float c[4], const uint32_t a[4],
                                         uint32_t b0, uint32_t b1) {
    asm volatile(
        "mma.sync.aligned.m16n8k16.row.col.f32.f16.f16.f32 "
        "{%0,%1,%2,%3}, {%4,%5,%6,%7}, {%8,%9}, {%0,%1,%2,%3};"
        : "+f"(c[0]), "+f"(c[1]), "+f"(c[2]), "+f"(c[3])
        : "r"(a[0]), "r"(a[1]), "r"(a[2]), "r"(a[3]), "r"(b0), "r"(b1));
}

// ---------------- accurate sincos for |a| <~ 200 (fast-math safe) -----------
__device__ __forceinline__ void rope_sincos(float a, float& s_out, float& c_out) {
    float j = rintf(a * 0.6366197723675814f);
    int   q = (int)j;
    float r = fmaf(j, -1.5703125f, a);
    r = fmaf(j, -4.837512969970703125e-4f, r);
    r = fmaf(j, -7.549789948768648e-8f, r);
    float r2 = r * r;
    float ss = -1.9515295891e-4f;
    ss = fmaf(ss, r2, 8.3321608736e-3f);
    ss = fmaf(ss, r2, -1.6666654611e-1f);
    ss = fmaf(ss * r2, r, r);
    float cc = 2.443315711809948e-5f;
    cc = fmaf(cc, r2, -1.388731625493765e-3f);
    cc = fmaf(cc, r2, 4.166664568298827e-2f);
    cc = fmaf(cc, r2, -0.5f);
    cc = fmaf(cc, r2, 1.0f);
    int qq = q & 3;
    float sv = (qq & 1) ? cc : ss;
    float cv = (qq & 1) ? ss : cc;
    if (qq & 2)       sv = -sv;
    if ((qq + 1) & 2) cv = -cv;
    s_out = sv; c_out = cv;
}
__device__ __forceinline__ float rope_inv_freq(int m) {
    return expf(-0.43858763676075163f * (float)m);   // exp(-m*ln(1e4)/21)
}
__device__ __forceinline__ void hf_split(float f, __half& h, __half& l) {
    h = __float2half_rn(f);
    l = __float2half_rn(f - __half2float(h));
}

// ---------------- conversion kernels -----------------------------------------
__global__ void conv_x_kernel(const float* __restrict__ x) {
    int idx = blockIdx.x * 256 + threadIdx.x;   // handles 4 elems
    float4 xv = ((const float4*)x)[idx];
    __half h0, h1, h2, h3, l0, l1, l2, l3;
    hf_split(xv.x, h0, l0); hf_split(xv.y, h1, l1);
    hf_split(xv.z, h2, l2); hf_split(xv.w, h3, l3);
    ((__half2*)g_xhi)[2 * idx]     = __halves2half2(h0, h1);
    ((__half2*)g_xhi)[2 * idx + 1] = __halves2half2(h2, h3);
    ((__half2*)g_xlo)[2 * idx]     = __halves2half2(l0, l1);
    ((__half2*)g_xlo)[2 * idx + 1] = __halves2half2(l2, l3);
}

__global__ void conv_w_kernel(const float* __restrict__ Wq, const float* __restrict__ Wk,
                              const float* __restrict__ Wv, const float* __restrict__ Wo) {
    int idx = blockIdx.x * 256 + threadIdx.x;   // 0 .. 512*512-1
    int mat = blockIdx.y;
    if (mat < 3) {
        const float* W = (mat == 0) ? Wq : (mat == 1 ? Wk : Wv);
        int jg = idx >> 9, k = idx & 511;
        g_whi[mat * 262144 + idx] =
            __float2half_rn(W[(((jg & 127) << 2) + (jg >> 7)) * 512 + k]);
    } else {
        int o = idx >> 9, j = idx & 511;
        g_wohi[idx] = __float2half_rn(Wo[o * 512 + ((j & 127) << 2) + (j >> 7)]);
    }
}

// ---------------- HMMA fp16 2-pass mainloop -----------------------------------
// CTA tile 128x128, K-step 64. smem per stage: Ahi 16K | Alo 16K | Bhi 16K.
// Warp grid 4(m) x 2(n): warp tile 32x64 -> A smem re-read 2x (was 4x).
#define TILE_BYTES  16384
#define STAGE_BYTES (3 * TILE_BYTES)
#define SMEM_BYTES  (2 * STAGE_BYTES)   // 98304 -> 2 CTAs/SM

__device__ __forceinline__ void load_stage(
    uint32_t smem_u32, int b,
    const __half* __restrict__ ahi, const __half* __restrict__ alo,
    const __half* __restrict__ bhi,
    int m0, int n0, int k0, int tid)
{
    const __half* src[3] = { ahi, alo, bhi };
    const uint32_t buf = smem_u32 + b * STAGE_BYTES;
#pragma unroll
    for (int t = 0; t < 3; t++) {
        const __half* g = src[t];
        const int r0 = (t < 2) ? m0 : n0;
        const uint32_t tb = buf + t * TILE_BYTES;
#pragma unroll
        for (int i = 0; i < 4; i++) {
            int cid = i * 256 + tid;          // 0..1023
            int row = cid >> 3, c = cid & 7;  // 128 rows x 8 chunks of 16B
            uint32_t dst = tb + row * 128 + ((c ^ (row & 7)) << 4);
            CP_ASYNC16(dst, g + (size_t)(r0 + row) * 512 + k0 + c * 8);
        }
    }
    CP_COMMIT();
}

// warp tile 32(m) x 64(n): acc[mi 0..1][nj 0..7][4]
__device__ __forceinline__ void compute_stage(
    uint32_t buf, int lane, int wm, int wn, float acc[2][8][4])
{
    const int g = lane >> 3, r = lane & 7;
    const int a_row0 = wm * 32 + ((g & 1) << 3) + r;
    const int a_ch0  = g >> 1;
    const int b_row0 = wn * 64 + ((g >> 1) << 3) + r;
    const int b_ch0  = g & 1;

#pragma unroll
    for (int kb = 0; kb < 4; kb++) {
        uint32_t ah[2][4], al[2][4];
#pragma unroll
        for (int mi = 0; mi < 2; mi++) {
            int row = a_row0 + mi * 16;
            int ch  = 2 * kb + a_ch0;
            uint32_t off = row * 128 + ((ch ^ (row & 7)) << 4);
            LDSM_X4(ah[mi], buf + off);
            LDSM_X4(al[mi], buf + TILE_BYTES + off);
        }
        uint32_t bh[4][4];   // [nb]: regs {0,1}=n8 frag 2nb, {2,3}=frag 2nb+1
#pragma unroll
        for (int nb = 0; nb < 4; nb++) {
            int row = b_row0 + nb * 16;
            int ch  = 2 * kb + b_ch0;
            uint32_t off = row * 128 + ((ch ^ (row & 7)) << 4);
            LDSM_X4(bh[nb], buf + 2 * TILE_BYTES + off);
        }
#pragma unroll
        for (int mi = 0; mi < 2; mi++) {
#pragma unroll
            for (int nj = 0; nj < 8; nj++) {
                uint32_t b0 = bh[nj >> 1][(nj & 1) * 2], b1 = bh[nj >> 1][(nj & 1) * 2 + 1];
                mma16816(acc[mi][nj], ah[mi], b0, b1);   // xh * wh
                mma16816(acc[mi][nj], al[mi], b0, b1);   // xl * wh
            }
        }
    }
}

__device__ __forceinline__ void gemm_mainloop(
    const __half* __restrict__ ahi, const __half* __restrict__ alo,
    const __half* __restrict__ bhi,
    int m0, int n0, uint32_t smem_u32, int tid, int lane, int wm, int wn,
    float acc[2][8][4])
{
#pragma unroll
    for (int mi = 0; mi < 2; mi++)
#pragma unroll
        for (int nj = 0; nj < 8; nj++)
#pragma unroll
            for (int q = 0; q < 4; q++) acc[mi][nj][q] = 0.f;

    load_stage(smem_u32, 0, ahi, alo, bhi, m0, n0, 0, tid);
#pragma unroll 1
    for (int s = 0; s < 8; s++) {
        if (s < 7) {
            load_stage(smem_u32, (s + 1) & 1, ahi, alo, bhi, m0, n0, (s + 1) * 64, tid);
            CP_WAIT(1);
        } else {
            CP_WAIT(0);
        }
        __syncthreads();
        compute_stage(smem_u32 + (s & 1) * STAGE_BYTES, lane, wm, wn, acc);
        __syncthreads();
    }
}

// ---------------- QKV GEMM (+bias, +q-scale, +RoPE, fp16 k/v out) -------------
__global__ __launch_bounds__(256, 2)
void qkv_tc_kernel(const float* __restrict__ pos,
                   const float* __restrict__ bq, const float* __restrict__ bk,
                   const float* __restrict__ bv)
{
    extern __shared__ __align__(1024) char smem[];
    const uint32_t smem_u32 = smem_to_u32(smem);
    const int tid  = threadIdx.x;
    const int lane = tid & 31;
    const int w    = tid >> 5;
    const int wm   = w >> 1, wn = w & 1;   // wm 0..3, wn 0..1
    const int m0   = blockIdx.x * 128;
    const int head = blockIdx.y;
    const int mode = blockIdx.z;           // 0=q, 1=k, 2=v
    const int n0   = head * 128;

    const __half* bh = g_whi + (size_t)mode * 262144;

    float acc[2][8][4];
    gemm_mainloop(g_xhi, g_xlo, bh, m0, n0, smem_u32, tid, lane, wm, wn, acc);

    // ---- epilogue ----
    const float* bias = (mode == 0) ? bq : (mode == 1 ? bk : bv);
    const float rs = (mode == 0) ? 0.08838834764831845f : 1.0f;   // 1/sqrt(128)
    const int tg = lane >> 2, tq = lane & 3;

#pragma unroll
    for (int mi = 0; mi < 2; mi++) {
#pragma unroll
        for (int half = 0; half < 2; half++) {
            int row = m0 + wm * 32 + mi * 16 + half * 8 + tg;
            if (row >= N_NODES) continue;
            float p0 = 0.f, p1 = 0.f, p2 = 0.f;
            if (mode != 2) {
                p0 = pos[row * 3 + 0]; p1 = pos[row * 3 + 1]; p2 = pos[row * 3 + 2];
            }
#pragma unroll
            for (int nj = 0; nj < 8; nj++) {
                int d = wn * 64 + nj * 8 + tq * 2;
                float v0 = (acc[mi][nj][half * 2 + 0] + __ldg(&bias[d * 4 + head])) * rs;
                float v1 = (acc[mi][nj][half * 2 + 1] + __ldg(&bias[(d + 1) * 4 + head])) * rs;
                if (mode != 2 && d < D_ROPE) {
                    int pp = (d >= 84) ? 2 : ((d >= 42) ? 1 : 0);
                    int mf = (d - pp * 42) >> 1;
                    float ps = (pp == 0) ? p0 : (pp == 1 ? p1 : p2);
                    float ang = ps * rope_inv_freq(mf);
                    float sn, cs;
                    rope_sincos(ang, sn, cs);
                    float ev = v0, od = v1;
                    v0 = ev * cs - od * sn;
                    v1 = ev * sn + od * cs;
                }
                size_t o = (size_t)row * 512 + head * DH + d;
                if (mode == 0) {
                    *(float2*)(g_q + o) = make_float2(v0, v1);
                } else {
                    __half2 hv = __halves2half2(__float2half_rn(v0), __float2half_rn(v1));
                    *(__half2*)(((mode == 1) ? g_kh : g_vh) + o) = hv;
                }
            }
        }
    }
}

// ---------------- output projection GEMM --------------------------------------
__global__ __launch_bounds__(256, 2)
void out_tc_kernel(const float* __restrict__ bo, float* __restrict__ out)
{
    extern __shared__ __align__(1024) char smem[];
    const uint32_t smem_u32 = smem_to_u32(smem);
    const int tid  = threadIdx.x;
    const int lane = tid & 31;
    const int w    = tid >> 5;
    const int wm   = w >> 1, wn = w & 1;
    const int m0   = blockIdx.x * 128;
    const int n0   = blockIdx.y * 128;

    const __half* bh = g_wohi + (size_t)n0 * 512;

    float acc[2][8][4];
    gemm_mainloop(g_yhi, g_ylo, bh, m0, 0, smem_u32, tid, lane, wm, wn, acc);

    const int tg = lane >> 2, tq = lane & 3;
#pragma unroll
    for (int mi = 0; mi < 2; mi++) {
#pragma unroll
        for (int half = 0; half < 2; half++) {
            int row = m0 + wm * 32 + mi * 16 + half * 8 + tg;
            if (row >= N_NODES) continue;
#pragma unroll
            for (int nj = 0; nj < 8; nj++) {
                int d = wn * 64 + nj * 8 + tq * 2;
                float v0 = acc[mi][nj][half * 2 + 0] + __ldg(&bo[n0 + d]);
                float v1 = acc[mi][nj][half * 2 + 1] + __ldg(&bo[n0 + d + 1]);
                *(float2*)(out + (size_t)row * 512 + n0 + d) = make_float2(v0, v1);
            }
        }
    }
}

// ---------------- per-node 16-edge softmax attention (fp16 k/v) ---------------
// block = node, warp = head, lane = 4 consecutive d's.
__global__ __launch_bounds__(128, 10)
void attn_kernel(const int* __restrict__ cols) {
    const int i    = blockIdx.x;
    const int hh   = threadIdx.x >> 5;
    const int lane = threadIdx.x & 31;

    // each lane holds edge (lane & 15)'s col; no smem, no block sync
    const int cown = __ldg(&cols[i * DEG + (lane & 15)]);

    const int off = i * 512 + hh * DH + lane * 4;
    const float4 q4 = *(const float4*)(g_q + off);

    float sc = -1e30f;
#pragma unroll
    for (int e = 0; e < DEG; e++) {
        int c = __shfl_sync(0xffffffffu, cown, e);
        uint2 kk = *(const uint2*)(g_kh + (size_t)c * 512 + hh * DH + lane * 4);
        float2 f01 = __half22float2(*reinterpret_cast<__half2*>(&kk.x));
        float2 f23 = __half22float2(*reinterpret_cast<__half2*>(&kk.y));
        float s = q4.x * f01.x;
        s = fmaf(q4.y, f01.y, s);
        s = fmaf(q4.z, f23.x, s);
        s = fmaf(q4.w, f23.y, s);
        s += __shfl_xor_sync(0xffffffffu, s, 16);
        s += __shfl_xor_sync(0xffffffffu, s, 8);
        s += __shfl_xor_sync(0xffffffffu, s, 4);
        s += __shfl_xor_sync(0xffffffffu, s, 2);
        s += __shfl_xor_sync(0xffffffffu, s, 1);
        if (lane == e) sc = s;   // lanes 0..15 hold the 16 scores
    }

    float mx = sc;
    mx = fmaxf(mx, __shfl_xor_sync(0xffffffffu, mx, 8));
    mx = fmaxf(mx, __shfl_xor_sync(0xffffffffu, mx, 4));
    mx = fmaxf(mx, __shfl_xor_sync(0xffffffffu, mx, 2));
    mx = fmaxf(mx, __shfl_xor_sync(0xffffffffu, mx, 1));

    float p = expf(sc - mx);
    float denom = p;
    denom += __shfl_xor_sync(0xffffffffu, denom, 8);
    denom += __shfl_xor_sync(0xffffffffu, denom, 4);
    denom += __shfl_xor_sync(0xffffffffu, denom, 2);
    denom += __shfl_xor_sync(0xffffffffu, denom, 1);
    float attnw = p / denom;

    float4 acc = make_float4(0.f, 0.f, 0.f, 0.f);
#pragma unroll
    for (int e = 0; e < DEG; e++) {
        int c = __shfl_sync(0xffffffffu, cown, e);
        float pe = __shfl_sync(0xffffffffu, attnw, e);
        uint2 vv = *(const uint2*)(g_vh + (size_t)c * 512 + hh * DH + lane * 4);
        float2 f01 = __half22float2(*reinterpret_cast<__half2*>(&vv.x));
        float2 f23 = __half22float2(*reinterpret_cast<__half2*>(&vv.y));
        acc.x = fmaf(pe, f01.x, acc.x);
        acc.y = fmaf(pe, f01.y, acc.y);
        acc.z = fmaf(pe, f23.x, acc.z);
        acc.w = fmaf(pe, f23.y, acc.w);
    }

    // split-fp16 store of y for the output projection
    __half h0, h1, h2, h3, l0, l1, l2, l3;
    hf_split(acc.x, h0, l0); hf_split(acc.y, h1, l1);
    hf_split(acc.z, h2, l2); hf_split(acc.w, h3, l3);
    __half2* yh = (__half2*)(g_yhi + off);
    __half2* yl = (__half2*)(g_ylo + off);
    yh[0] = __halves2half2(h0, h1);
    yh[1] = __halves2half2(h2, h3);
    yl[0] = __halves2half2(l0, l1);
    yl[1] = __halves2half2(l2, l3);
}

// -----------------------------------------------------------------------------
extern "C" void kernel_launch(void* const* d_in, const int* in_sizes, int n_in,
                              void* d_out, int out_size) {
    const float* x   = (const float*)d_in[0];
    const float* pos = (const float*)d_in[1];
    // d_in[2] = rows (implicit: node i owns edges [16i, 16i+16))
    const int*   cols = (const int*)d_in[3];
    const float* Wq = (const float*)d_in[4];
    const float* bq = (const float*)d_in[5];
    const float* Wk = (const float*)d_in[6];
    const float* bk = (const float*)d_in[7];
    const float* Wv = (const float*)d_in[8];
    const float* bv = (const float*)d_in[9];
    const float* Wo = (const float*)d_in[10];
    const float* bo = (const float*)d_in[11];
    float* out = (float*)d_out;

    static bool attr_set = false;
    if (!attr_set) {
        cudaFuncSetAttribute(qkv_tc_kernel, cudaFuncAttributeMaxDynamicSharedMemorySize, SMEM_BYTES);
        cudaFuncSetAttribute(out_tc_kernel, cudaFuncAttributeMaxDynamicSharedMemorySize, SMEM_BYTES);
        attr_set = true;
    }

    conv_x_kernel<<<(N_NODES * 512 / 4) / 256, 256>>>(x);
    conv_w_kernel<<<dim3(512 * 512 / 256, 4), 256>>>(Wq, Wk, Wv, Wo);

    qkv_tc_kernel<<<dim3(MT, NHEAD, 3), 256, SMEM_BYTES>>>(pos, bq, bk, bv);

    attn_kernel<<<N_NODES, 128>>>(cols);

    out_tc_kernel<<<dim3(MT, NHEAD), 256, SMEM_BYTES>>>(bo, out);
}